// round 16
// baseline (speedup 1.0000x reference)
#include <cuda_runtime.h>
#include <cuda_fp16.h>
#include <math.h>
#include <float.h>
#include <stdint.h>

#define NN 50000
#define EE 300000
#define BB 256
#define FF 128
#define F2C 256
#define AA 2016
#define LL 10
#define NEGS 0.01f
#define EPSV 1e-5f

#define SCANB ((NN + 256) / 256)
#define MT 128
#define NB ((NN + MT - 1) / MT)     /* 391 node blocks */
#define NSTAGE 32                   /* K'' = 1024 = 32 * 32 (fp16 2-term split) */
#define NSLOT 6                     /* smem ring slots (16KB each) */
#define SMEMB (NSLOT * 16384)       /* 96KB dyn smem */

/* ---------------- scratch ----------------
   Slab layout for fp16 operands: chunk = [128 rows][32 k] = 8KB, SW64-swizzled.
   agg/hin: per node block nb, 16 chunks: j 0..7 = hi (k cols 32j..), j 8..15 = lo. */
__device__ float g_hA[NN * F2C];                            /* final-layer h only (head input) */
__device__ __half g_aggT[(size_t)NB * 16 * 4096];
__device__ __half g_hinA[(size_t)NB * 16 * 4096];
__device__ __half g_hinB[(size_t)NB * 16 * 4096];
__device__ __half g_Bpack[(size_t)LL * NSTAGE * 2 * 4096];  /* [l][s][bn][chunk 8KB] */
__device__ float g_invdeg[NN];
__device__ int   g_deg[NN];
__device__ int   g_off[NN + 1];
__device__ int   g_cur[NN];
__device__ int   g_srcs[EE];
__device__ int   g_gcnt[BB];
__device__ int   g_gstart[BB];
__device__ int   g_bsum[SCANB];

/* ---------------- helpers ---------------- */
__device__ __forceinline__ uint32_t smem_u32(const void* p) {
    uint32_t a;
    asm("{ .reg .u64 t; cvta.to.shared.u64 t, %1; cvt.u32.u64 %0, t; }" : "=r"(a) : "l"(p));
    return a;
}
/* byte offset of (row, kk) inside an 8KB slab chunk, SW64-swizzled (16B units). */
__device__ __host__ __forceinline__ uint32_t slab_off(int row, int kk) {
    int c = kk >> 3;
    return (uint32_t)(row * 64 + (((c ^ ((row & 6) >> 1))) << 4) + ((kk & 7) << 1));
}
__device__ __forceinline__ void mbar_init(uint32_t a, uint32_t cnt) {
    asm volatile("mbarrier.init.shared.b64 [%0], %1;" :: "r"(a), "r"(cnt) : "memory");
}
__device__ __forceinline__ void mbar_wait(uint32_t a, uint32_t parity) {
    asm volatile(
        "{\n\t.reg .pred P;\n"
        "W_%=:\n\t"
        "mbarrier.try_wait.parity.acquire.cta.shared::cta.b64 P, [%0], %1, 0x989680;\n\t"
        "@P bra.uni D_%=;\n\t"
        "bra.uni W_%=;\n"
        "D_%=:\n\t}"
        :: "r"(a), "r"(parity) : "memory");
}
__device__ __forceinline__ void mbar_arrive(uint32_t a) {
    asm volatile("mbarrier.arrive.shared.b64 _, [%0];" :: "r"(a) : "memory");
}
__device__ __forceinline__ void mbar_expect(uint32_t a, uint32_t bytes) {
    asm volatile("mbarrier.arrive.expect_tx.shared.b64 _, [%0], %1;"
                 :: "r"(a), "r"(bytes) : "memory");
}
__device__ __forceinline__ void bulkcp(uint32_t dst, const void* src, uint32_t bytes, uint32_t mb) {
    asm volatile("cp.async.bulk.shared::cluster.global.mbarrier::complete_tx::bytes [%0], [%1], %2, [%3];"
                 :: "r"(dst), "l"(src), "r"(bytes), "r"(mb) : "memory");
}
#define LDSM4(r, addr) \
    asm volatile("ldmatrix.sync.aligned.m8n8.x4.shared.b16 {%0,%1,%2,%3}, [%4];" \
                 : "=r"((r)[0]), "=r"((r)[1]), "=r"((r)[2]), "=r"((r)[3]) : "r"(addr))
#define MMA16816(d, a, b0, b1) \
    asm volatile("mma.sync.aligned.m16n8k16.row.col.f32.f16.f16.f32 " \
                 "{%0,%1,%2,%3}, {%4,%5,%6,%7}, {%8,%9}, {%0,%1,%2,%3};" \
                 : "+f"((d)[0]), "+f"((d)[1]), "+f"((d)[2]), "+f"((d)[3]) \
                 : "r"((a)[0]), "r"((a)[1]), "r"((a)[2]), "r"((a)[3]), "r"(b0), "r"(b1))

/* ---------------- setup kernels ---------------- */
__global__ void k_zero() {
    int i = blockIdx.x * blockDim.x + threadIdx.x;
    if (i < NN) g_deg[i] = 0;
    if (i < BB) g_gcnt[i] = 0;
}

__global__ void k_embed(const int* __restrict__ x, const float* __restrict__ emb) {
    int idx = blockIdx.x * blockDim.x + threadIdx.x;
    if (idx >= NN * F2C) return;
    int node = idx >> 8;
    int c = idx & 255;
    int tok = x[node * 2 + (c >> 7)];
    float v = emb[tok * FF + (c & 127)];
    __half hi = __float2half_rn(v);
    float lo = v - __half2float(hi);
    size_t cb = ((size_t)(node >> 7) * 16 + (c >> 5)) * 8192;
    uint32_t off = slab_off(node & 127, c & 31);
    *(__half*)((char*)g_hinA + cb + off) = hi;
    *(__half*)((char*)g_hinA + cb + 8 * 8192 + off) = __float2half_rn(lo);
}

/* edge degrees + per-graph node counts in one kernel */
__global__ void k_deg(const int* __restrict__ ei, const int* __restrict__ batch) {
    int e = blockIdx.x * blockDim.x + threadIdx.x;
    if (e < EE) atomicAdd(&g_deg[ei[EE + e]], 1);
    if (e < NN) atomicAdd(&g_gcnt[batch[e]], 1);
}

__global__ void k_scan_a() {
    __shared__ int sh[256];
    int b = blockIdx.x, t = threadIdx.x;
    int i = b * 256 + t;
    int v = (i < NN) ? g_deg[i] : 0;
    sh[t] = v;
    __syncthreads();
    for (int o = 1; o < 256; o <<= 1) {
        int add = (t >= o) ? sh[t - o] : 0;
        __syncthreads();
        sh[t] += add;
        __syncthreads();
    }
    if (i <= NN) g_off[i] = sh[t] - v;
    if (t == 255) g_bsum[b] = sh[255];
}
/* block 0: scan of g_bsum; block 1: scan of g_gcnt -> g_gstart */
__global__ void k_scan_b2() {
    __shared__ int sh[256];
    int t = threadIdx.x;
    int v;
    if (blockIdx.x == 0) v = (t < SCANB) ? g_bsum[t] : 0;
    else                 v = g_gcnt[t];
    sh[t] = v;
    __syncthreads();
    for (int o = 1; o < 256; o <<= 1) {
        int add = (t >= o) ? sh[t - o] : 0;
        __syncthreads();
        sh[t] += add;
        __syncthreads();
    }
    if (blockIdx.x == 0) { if (t < SCANB) g_bsum[t] = sh[t] - v; }
    else                 g_gstart[t] = sh[t] - v;
}
/* scan finalize + prep (merged) */
__global__ void k_scan_c() {
    int i = blockIdx.x * blockDim.x + threadIdx.x;
    if (i <= NN) {
        int off = g_off[i] + g_bsum[i >> 8];
        g_off[i] = off;
        if (i < NN) {
            g_cur[i] = off;
            int d = g_deg[i];
            g_invdeg[i] = 1.0f / (float)(d > 0 ? d : 1);
        }
    }
}

__global__ void k_scatter(const int* __restrict__ ei) {
    int e = blockIdx.x * blockDim.x + threadIdx.x;
    if (e >= EE) return;
    int d = ei[EE + e];
    int pos = atomicAdd(&g_cur[d], 1);
    g_srcs[pos] = ei[e];
}

__global__ void k_sortseg() {
    int n = blockIdx.x * blockDim.x + threadIdx.x;
    if (n >= NN) return;
    int beg = g_off[n], end = g_off[n + 1];
    for (int i = beg + 1; i < end; i++) {
        int v = g_srcs[i];
        int j = i - 1;
        while (j >= beg && g_srcs[j] > v) { g_srcs[j + 1] = g_srcs[j]; j--; }
        g_srcs[j + 1] = v;
    }
}

/* B pack over 32 K32-stages (W single fp16, activations carry the 2-term split):
   regions reg = s>>3: 0:hin_hi*Wr 1:hin_lo*Wr 2:agg_hi*Wl 3:agg_lo*Wl */
__global__ void k_bpack(const float* __restrict__ Wl, const float* __restrict__ Wr) {
    int idx = blockIdx.x * blockDim.x + threadIdx.x;
    if (idx >= LL * NSTAGE * 2 * 4096) return;
    int kk = idx & 31;
    int row = (idx >> 5) & 127;
    int bn = (idx >> 12) & 1;
    int rest = idx >> 13;
    int s = rest % NSTAGE;
    int l = rest / NSTAGE;
    int reg = s >> 3;
    int wk = (s & 7) * 32 + kk;
    int n = bn * 128 + row;
    const float* W = (reg < 2) ? Wr : Wl;
    float w = W[((size_t)l * 256 + wk) * 256 + n];
    size_t cb = ((size_t)((l * NSTAGE + s) * 2 + bn)) * 8192;
    *(__half*)((char*)g_Bpack + cb + slab_off(row, kk)) = __float2half_rn(w);
}

/* mean-aggregate neighbors from hi/lo fp16 slabs -> hi/lo fp16 into g_aggT.
   One block per node, 64 threads x 4 channels (2 x uint2 per edge). */
__global__ __launch_bounds__(64) void k_aggregate(const __half* __restrict__ hin) {
    int n = blockIdx.x;
    int t = threadIdx.x;        /* 0..63 */
    int c = t * 4;
    int beg = g_off[n], end = g_off[n + 1];
    const int chunk = c >> 5;
    const int kk = c & 31;
    const char* base = (const char*)hin;
    float s0 = 0.0f, s1 = 0.0f, s2 = 0.0f, s3 = 0.0f;
    for (int i = beg; i < end; i++) {
        int sn = g_srcs[i];
        size_t cb = ((size_t)(sn >> 7) * 16 + chunk) * 8192;
        uint32_t off = slab_off(sn & 127, kk);
        uint2 hp = *(const uint2*)(base + cb + off);
        uint2 lp = *(const uint2*)(base + cb + 65536 + off);
        float2 h01 = __half22float2(*reinterpret_cast<const __half2*>(&hp.x));
        float2 h23 = __half22float2(*reinterpret_cast<const __half2*>(&hp.y));
        float2 l01 = __half22float2(*reinterpret_cast<const __half2*>(&lp.x));
        float2 l23 = __half22float2(*reinterpret_cast<const __half2*>(&lp.y));
        s0 += h01.x + l01.x;
        s1 += h01.y + l01.y;
        s2 += h23.x + l23.x;
        s3 += h23.y + l23.y;
    }
    float inv = g_invdeg[n];
    float a0 = s0 * inv, a1 = s1 * inv, a2 = s2 * inv, a3 = s3 * inv;
    __half h0 = __float2half_rn(a0), h1 = __float2half_rn(a1);
    __half h2 = __float2half_rn(a2), h3 = __float2half_rn(a3);
    __half l0 = __float2half_rn(a0 - __half2float(h0));
    __half l1 = __float2half_rn(a1 - __half2float(h1));
    __half l2 = __float2half_rn(a2 - __half2float(h2));
    __half l3 = __float2half_rn(a3 - __half2float(h3));
    uint2 hp, lp;
    hp.x = (uint32_t)__half_as_ushort(h0) | ((uint32_t)__half_as_ushort(h1) << 16);
    hp.y = (uint32_t)__half_as_ushort(h2) | ((uint32_t)__half_as_ushort(h3) << 16);
    lp.x = (uint32_t)__half_as_ushort(l0) | ((uint32_t)__half_as_ushort(l1) << 16);
    lp.y = (uint32_t)__half_as_ushort(l2) | ((uint32_t)__half_as_ushort(l3) << 16);
    size_t cb = ((size_t)(n >> 7) * 16 + chunk) * 8192;
    uint32_t off = slab_off(n & 127, kk);
    *(uint2*)((char*)g_aggT + cb + off) = hp;
    *(uint2*)((char*)g_aggT + cb + 8 * 8192 + off) = lp;
}

/* ---------------- SAGE GEMM: warp-specialized producer + mbarrier ring ----------------
   C[128,128] = A''[128,1024] @ B''[1024,128], grid (391, 2).
   Warps 0..7 compute; warp 8 issues bulk copies. 6-slot ring, full/empty mbarriers.
   Epilogue: layers 0..8 write hin slabs only; layer 9 writes fp32 h (head input). */
__global__ __launch_bounds__(288, 2)
void k_sage_mma(int layer, const float* __restrict__ bl,
                float* __restrict__ hnext,
                const __half* __restrict__ hin_in,
                __half* __restrict__ hin_out) {
    extern __shared__ char smem[];
    __shared__ float sbias[128];
    __shared__ __align__(8) unsigned long long mb_full[NSLOT], mb_empty[NSLOT];
    const int tid = threadIdx.x;
    const int wid = tid >> 5;
    const int lane = tid & 31;
    const int nb = blockIdx.x;
    const int bm = nb * MT;
    const int bn = blockIdx.y;
    const uint32_t sb = smem_u32(smem);

    if (tid == 0) {
#pragma unroll
        for (int i = 0; i < NSLOT; i++) {
            mbar_init(smem_u32(&mb_full[i]), 1);
            mbar_init(smem_u32(&mb_empty[i]), 8);
        }
    }
    if (tid < 128) sbias[tid] = bl[bn * 128 + tid];
    __syncthreads();

    float acc[2][8][4];
#pragma unroll
    for (int i = 0; i < 2; i++)
#pragma unroll
        for (int j = 0; j < 8; j++)
#pragma unroll
            for (int q = 0; q < 4; q++) acc[i][j][q] = 0.0f;

    if (wid == 8) {
        /* producer warp: one elected thread issues all copies */
        if (lane == 0) {
            int slot = 0, pe = 1;
            for (int s = 0; s < NSTAGE; s++) {
                if (s >= NSLOT) mbar_wait(smem_u32(&mb_empty[slot]), pe);
                uint32_t mb = smem_u32(&mb_full[slot]);
                mbar_expect(mb, 16384);
                int reg = s >> 3;
                int j = s & 7;
                int chunk = (reg & 1) ? 8 + j : j;
                const __half* base = (reg < 2) ? hin_in : g_aggT;
                bulkcp(sb + slot * 16384, base + ((size_t)(nb * 16 + chunk)) * 4096, 8192, mb);
                const __half* bsrc =
                    g_Bpack + ((size_t)((layer * NSTAGE + s) * 2 + bn)) * 4096;
                bulkcp(sb + slot * 16384 + 8192, bsrc, 8192, mb);
                if (++slot == NSLOT) { slot = 0; pe ^= 1; }
            }
        }
    } else {
        const int wm = wid >> 1;
        const int wn = wid & 1;
        const int rowlane = lane & 15;
        const int c16 = lane >> 4;

        int slot = 0, pf = 0;
        for (int s = 0; s < NSTAGE; s++) {
            mbar_wait(smem_u32(&mb_full[slot]), pf);
            uint32_t Abase = sb + slot * 16384;
            uint32_t Bbase = Abase + 8192;
#pragma unroll
            for (int ks = 0; ks < 2; ks++) {
                uint32_t a[2][4], bb[4][4];
#pragma unroll
                for (int mi = 0; mi < 2; mi++) {
                    int row = wm * 32 + mi * 16 + rowlane;
                    int c = ks * 2 + c16;
                    LDSM4(a[mi], Abase + row * 64 + ((c ^ ((row & 6) >> 1)) << 4));
                }
#pragma unroll
                for (int nj = 0; nj < 4; nj++) {
                    int row = wn * 64 + nj * 16 + rowlane;
                    int c = ks * 2 + c16;
                    LDSM4(bb[nj], Bbase + row * 64 + ((c ^ ((row & 6) >> 1)) << 4));
                }
#pragma unroll
                for (int mi = 0; mi < 2; mi++)
#pragma unroll
                    for (int nj = 0; nj < 4; nj++) {
                        MMA16816(acc[mi][nj * 2], a[mi], bb[nj][0], bb[nj][2]);
                        MMA16816(acc[mi][nj * 2 + 1], a[mi], bb[nj][1], bb[nj][3]);
                    }
            }
            if (lane == 0) mbar_arrive(smem_u32(&mb_empty[slot]));
            if (++slot == NSLOT) { slot = 0; pf ^= 1; }
        }
    }
    __syncthreads();

    /* acc -> smem Cs */
    float* Cs = (float*)smem;
    if (wid != 8) {
        const int wm = wid >> 1, wn = wid & 1;
#pragma unroll
        for (int mi = 0; mi < 2; mi++)
#pragma unroll
            for (int jn = 0; jn < 8; jn++) {
                int r1 = wm * 32 + mi * 16 + (lane >> 2);
                int cc = wn * 64 + jn * 8 + (lane & 3) * 2;
                Cs[r1 * 132 + cc]           = acc[mi][jn][0];
                Cs[r1 * 132 + cc + 1]       = acc[mi][jn][1];
                Cs[(r1 + 8) * 132 + cc]     = acc[mi][jn][2];
                Cs[(r1 + 8) * 132 + cc + 1] = acc[mi][jn][3];
            }
    }
    __syncthreads();

    /* epilogue: bias + leaky+residual */
    const bool wantHin = (layer != LL - 1);
    const bool wantH   = (layer == LL - 1);
    if (tid < 256) {
#pragma unroll 1
        for (int it = 0; it < 16; it++) {
            int idx = tid + it * 256;
            int row = idx >> 5;
            int c4 = (idx & 31) * 4;
            int gr = bm + row;
            if (gr < NN) {
                float x0 = Cs[row * 132 + c4 + 0] + sbias[c4 + 0];
                float x1 = Cs[row * 132 + c4 + 1] + sbias[c4 + 1];
                float x2 = Cs[row * 132 + c4 + 2] + sbias[c4 + 2];
                float x3 = Cs[row * 132 + c4 + 3] + sbias[c4 + 3];
                x0 = (x0 > 0.0f) ? 2.0f * x0 : (1.0f + NEGS) * x0;
                x1 = (x1 > 0.0f) ? 2.0f * x1 : (1.0f + NEGS) * x1;
                x2 = (x2 > 0.0f) ? 2.0f * x2 : (1.0f + NEGS) * x2;
                x3 = (x3 > 0.0f) ? 2.0f * x3 : (1.0f + NEGS) * x3;
                int col = bn * 128 + c4;
                if (wantH)
                    *(float4*)(hnext + (size_t)gr * 256 + col) = make_float4(x0, x1, x2, x3);
                if (wantHin) {
                    __half h0 = __float2half_rn(x0), h1 = __float2half_rn(x1);
                    __half h2 = __float2half_rn(x2), h3 = __float2half_rn(x3);
                    uint2 hu, lu;
                    hu.x = (uint32_t)__half_as_ushort(h0) | ((uint32_t)__half_as_ushort(h1) << 16);
                    hu.y = (uint32_t)__half_as_ushort(h2) | ((uint32_t)__half_as_ushort(h3) << 16);
                    __half q0 = __float2half_rn(x0 - __half2float(h0));
                    __half q1 = __float2half_rn(x1 - __half2float(h1));
                    __half q2 = __float2half_rn(x2 - __half2float(h2));
                    __half q3 = __float2half_rn(x3 - __half2float(h3));
                    lu.x = (uint32_t)__half_as_ushort(q0) | ((uint32_t)__half_as_ushort(q1) << 16);
                    lu.y = (uint32_t)__half_as_ushort(q2) | ((uint32_t)__half_as_ushort(q3) << 16);
                    size_t cb = ((size_t)(gr >> 7) * 16 + (col >> 5)) * 8192;
                    uint32_t off = slab_off(gr & 127, col & 31);
                    *(uint2*)((char*)hin_out + cb + off) = hu;
                    *(uint2*)((char*)hin_out + cb + 8 * 8192 + off) = lu;
                }
            }
        }
    }
}

/* ---------------- fused head: GraphNorm + SoftmaxAggregation + 3-layer MLP ----------------
   One block per graph b, 256 threads. g/y1/y2 live in smem. */
__global__ __launch_bounds__(256) void k_head(
    const float* __restrict__ gw, const float* __restrict__ gb,
    const float* __restrict__ gs, const float* __restrict__ tptr,
    const float* __restrict__ W1, const float* __restrict__ b1,
    const float* __restrict__ W2, const float* __restrict__ b2,
    const float* __restrict__ W3, const float* __restrict__ b3,
    float* __restrict__ out) {
    __shared__ float sg[F2C];
    __shared__ float sy1[F2C];
    __shared__ float sy2[FF];
    int b = blockIdx.x;
    int c = threadIdx.x;
    int start = g_gstart[b], cnt = g_gcnt[b];
    float cntf = (cnt > 0) ? (float)cnt : 1.0f;
    float t = tptr[0];

    /* GraphNorm (per channel c) */
    float s = 0.0f;
    for (int i = 0; i < cnt; i++) s += g_hA[(size_t)(start + i) * F2C + c];
    float ms = (s / cntf) * gs[c];

    float v = 0.0f;
    for (int i = 0; i < cnt; i++) {
        float o = g_hA[(size_t)(start + i) * F2C + c] - ms;
        v += o * o;
    }
    float inv = 1.0f / sqrtf(v / cntf + EPSV);
    float w = gw[c], bias = gb[c];
    float m = -FLT_MAX;
    for (int i = 0; i < cnt; i++) {
        size_t idx = (size_t)(start + i) * F2C + c;
        float hv = w * (g_hA[idx] - ms) * inv + bias;
        g_hA[idx] = hv;
        m = fmaxf(m, hv * t);
    }

    /* softmax aggregation -> g */
    float se = 0.0f, sh = 0.0f;
    for (int i = 0; i < cnt; i++) {
        float hv = g_hA[(size_t)(start + i) * F2C + c];
        float e = expf(hv * t - m);
        se += e;
        sh += e * hv;
    }
    sg[c] = (cnt > 0) ? (sh / se) : 0.0f;
    __syncthreads();

    /* MLP1: y1 = leaky(g @ W1 + b1), 256 wide */
    {
        float acc = b1[c];
#pragma unroll 8
        for (int k = 0; k < F2C; k++) acc += sg[k] * W1[k * F2C + c];
        sy1[c] = (acc > 0.0f) ? acc : NEGS * acc;
    }
    __syncthreads();

    /* MLP2: y2 = leaky(y1 @ W2 + b2), 128 wide */
    if (c < FF) {
        float acc = b2[c];
#pragma unroll 8
        for (int k = 0; k < F2C; k++) acc += sy1[k] * W2[k * FF + c];
        sy2[c] = (acc > 0.0f) ? acc : NEGS * acc;
    }
    __syncthreads();

    /* MLP3: out = y2 @ W3 + b3, 2016 wide (8 cols per thread) */
    {
        float acc[8];
#pragma unroll
        for (int r = 0; r < 8; r++) {
            int idx = c + 256 * r;
            acc[r] = (idx < AA) ? b3[idx] : 0.0f;
        }
        for (int k = 0; k < FF; k++) {
            float rv = sy2[k];
            const float* wr = W3 + (size_t)k * AA;
#pragma unroll
            for (int r = 0; r < 8; r++) {
                int idx = c + 256 * r;
                if (idx < AA) acc[r] += rv * wr[idx];
            }
        }
#pragma unroll
        for (int r = 0; r < 8; r++) {
            int idx = c + 256 * r;
            if (idx < AA) out[b * AA + idx] = acc[r];
        }
    }
}

/* ---------------- launch ---------------- */
extern "C" void kernel_launch(void* const* d_in, const int* in_sizes, int n_in,
                              void* d_out, int out_size) {
    const int*   x     = (const int*)d_in[0];
    const int*   ei    = (const int*)d_in[1];
    const int*   batch = (const int*)d_in[2];
    const float* emb   = (const float*)d_in[3];
    const float* Wl    = (const float*)d_in[4];
    const float* bl    = (const float*)d_in[5];
    const float* Wr    = (const float*)d_in[6];
    const float* gw    = (const float*)d_in[7];
    const float* gb    = (const float*)d_in[8];
    const float* gs    = (const float*)d_in[9];
    const float* t     = (const float*)d_in[10];
    const float* W1    = (const float*)d_in[11];
    const float* b1    = (const float*)d_in[12];
    const float* W2    = (const float*)d_in[13];
    const float* b2    = (const float*)d_in[14];
    const float* W3    = (const float*)d_in[15];
    const float* b3    = (const float*)d_in[16];
    float* out = (float*)d_out;

    cudaFuncSetAttribute(k_sage_mma, cudaFuncAttributeMaxDynamicSharedMemorySize, SMEMB);

    __half* hinbuf[2];
    cudaGetSymbolAddress((void**)&hinbuf[0], g_hinA);
    cudaGetSymbolAddress((void**)&hinbuf[1], g_hinB);
    float* hA;
    cudaGetSymbolAddress((void**)&hA, g_hA);

    /* graph structure + packing */
    k_zero<<<(NN + 255) / 256, 256>>>();
    k_embed<<<(NN * F2C + 255) / 256, 256>>>(x, emb);
    k_deg<<<(EE + 255) / 256, 256>>>(ei, batch);
    k_scan_a<<<SCANB, 256>>>();
    k_scan_b2<<<2, 256>>>();
    k_scan_c<<<(NN + 1 + 255) / 256, 256>>>();
    k_scatter<<<(EE + 255) / 256, 256>>>(ei);
    k_sortseg<<<(NN + 255) / 256, 256>>>();
    k_bpack<<<(LL * NSTAGE * 2 * 4096 + 255) / 256, 256>>>(Wl, Wr);

    /* 10 SAGE layers: slab-gather aggregate + warp-specialized tensor GEMM */
    dim3 ggrid(NB, 2);
    for (int l = 0; l < LL; l++) {
        int p = l & 1;
        k_aggregate<<<NN, 64>>>((const __half*)hinbuf[p]);
        k_sage_mma<<<ggrid, 288, SMEMB>>>(l, bl + l * F2C, hA,
                                          hinbuf[p], hinbuf[p ^ 1]);
    }

    /* fused GraphNorm + softmax aggregation + MLP head */
    k_head<<<BB, 256>>>(gw, gb, gs, t, W1, b1, W2, b2, W3, b3, out);
}

// round 17
// speedup vs baseline: 1.5137x; 1.5137x over previous
#include <cuda_runtime.h>
#include <cuda_fp16.h>
#include <math.h>
#include <float.h>
#include <stdint.h>

#define NN 50000
#define EE 300000
#define BB 256
#define FF 128
#define F2C 256
#define AA 2016
#define LL 10
#define NEGS 0.01f
#define EPSV 1e-5f

#define SCANB ((NN + 256) / 256)
#define MT 128
#define NB ((NN + MT - 1) / MT)     /* 391 node blocks */
#define NSTAGE 32                   /* K'' = 1024 = 32 * 32 (fp16 2-term split) */
#define NSLOT 6                     /* smem ring slots (16KB each) */
#define SMEMB (NSLOT * 16384)       /* 96KB dyn smem */

/* ---------------- scratch ----------------
   Slab layout for fp16 operands: chunk = [128 rows][32 k] = 8KB, SW64-swizzled.
   agg/hin: per node block nb, 16 chunks: j 0..7 = hi (k cols 32j..), j 8..15 = lo. */
__device__ float g_hA[NN * F2C];
__device__ float g_hB[NN * F2C];
__device__ __half g_aggT[(size_t)NB * 16 * 4096];
__device__ __half g_hinA[(size_t)NB * 16 * 4096];
__device__ __half g_hinB[(size_t)NB * 16 * 4096];
__device__ __half g_Bpack[(size_t)LL * NSTAGE * 2 * 4096];  /* [l][s][bn][chunk 8KB] */
__device__ float g_invdeg[NN];
__device__ int   g_deg[NN];
__device__ int   g_off[NN + 1];
__device__ int   g_cur[NN];
__device__ int   g_srcs[EE];
__device__ int   g_gcnt[BB];
__device__ int   g_gstart[BB];
__device__ int   g_bsum[SCANB];

/* ---------------- helpers ---------------- */
__device__ __forceinline__ uint32_t smem_u32(const void* p) {
    uint32_t a;
    asm("{ .reg .u64 t; cvta.to.shared.u64 t, %1; cvt.u32.u64 %0, t; }" : "=r"(a) : "l"(p));
    return a;
}
/* byte offset of (row, kk) inside an 8KB slab chunk, SW64-swizzled (16B units). */
__device__ __host__ __forceinline__ uint32_t slab_off(int row, int kk) {
    int c = kk >> 3;
    return (uint32_t)(row * 64 + (((c ^ ((row & 6) >> 1))) << 4) + ((kk & 7) << 1));
}
__device__ __forceinline__ void mbar_init(uint32_t a, uint32_t cnt) {
    asm volatile("mbarrier.init.shared.b64 [%0], %1;" :: "r"(a), "r"(cnt) : "memory");
}
__device__ __forceinline__ void mbar_wait(uint32_t a, uint32_t parity) {
    asm volatile(
        "{\n\t.reg .pred P;\n"
        "W_%=:\n\t"
        "mbarrier.try_wait.parity.acquire.cta.shared::cta.b64 P, [%0], %1, 0x989680;\n\t"
        "@P bra.uni D_%=;\n\t"
        "bra.uni W_%=;\n"
        "D_%=:\n\t}"
        :: "r"(a), "r"(parity) : "memory");
}
__device__ __forceinline__ void mbar_arrive(uint32_t a) {
    asm volatile("mbarrier.arrive.shared.b64 _, [%0];" :: "r"(a) : "memory");
}
__device__ __forceinline__ void mbar_expect(uint32_t a, uint32_t bytes) {
    asm volatile("mbarrier.arrive.expect_tx.shared.b64 _, [%0], %1;"
                 :: "r"(a), "r"(bytes) : "memory");
}
__device__ __forceinline__ void bulkcp(uint32_t dst, const void* src, uint32_t bytes, uint32_t mb) {
    asm volatile("cp.async.bulk.shared::cluster.global.mbarrier::complete_tx::bytes [%0], [%1], %2, [%3];"
                 :: "r"(dst), "l"(src), "r"(bytes), "r"(mb) : "memory");
}
#define LDSM4(r, addr) \
    asm volatile("ldmatrix.sync.aligned.m8n8.x4.shared.b16 {%0,%1,%2,%3}, [%4];" \
                 : "=r"((r)[0]), "=r"((r)[1]), "=r"((r)[2]), "=r"((r)[3]) : "r"(addr))
#define MMA16816(d, a, b0, b1) \
    asm volatile("mma.sync.aligned.m16n8k16.row.col.f32.f16.f16.f32 " \
                 "{%0,%1,%2,%3}, {%4,%5,%6,%7}, {%8,%9}, {%0,%1,%2,%3};" \
                 : "+f"((d)[0]), "+f"((d)[1]), "+f"((d)[2]), "+f"((d)[3]) \
                 : "r"((a)[0]), "r"((a)[1]), "r"((a)[2]), "r"((a)[3]), "r"(b0), "r"(b1))

/* ---------------- setup kernels ---------------- */
__global__ void k_zero() {
    int i = blockIdx.x * blockDim.x + threadIdx.x;
    if (i < NN) g_deg[i] = 0;
    if (i < BB) g_gcnt[i] = 0;
}

__global__ void k_embed(const int* __restrict__ x, const float* __restrict__ emb) {
    int idx = blockIdx.x * blockDim.x + threadIdx.x;
    if (idx >= NN * F2C) return;
    int node = idx >> 8;
    int c = idx & 255;
    int tok = x[node * 2 + (c >> 7)];
    float v = emb[tok * FF + (c & 127)];
    g_hA[idx] = v;
    __half hi = __float2half_rn(v);
    float lo = v - __half2float(hi);
    size_t cb = ((size_t)(node >> 7) * 16 + (c >> 5)) * 8192;
    uint32_t off = slab_off(node & 127, c & 31);
    *(__half*)((char*)g_hinA + cb + off) = hi;
    *(__half*)((char*)g_hinA + cb + 8 * 8192 + off) = __float2half_rn(lo);
}

/* edge degrees + per-graph node counts in one kernel */
__global__ void k_deg(const int* __restrict__ ei, const int* __restrict__ batch) {
    int e = blockIdx.x * blockDim.x + threadIdx.x;
    if (e < EE) atomicAdd(&g_deg[ei[EE + e]], 1);
    if (e < NN) atomicAdd(&g_gcnt[batch[e]], 1);
}

__global__ void k_scan_a() {
    __shared__ int sh[256];
    int b = blockIdx.x, t = threadIdx.x;
    int i = b * 256 + t;
    int v = (i < NN) ? g_deg[i] : 0;
    sh[t] = v;
    __syncthreads();
    for (int o = 1; o < 256; o <<= 1) {
        int add = (t >= o) ? sh[t - o] : 0;
        __syncthreads();
        sh[t] += add;
        __syncthreads();
    }
    if (i <= NN) g_off[i] = sh[t] - v;
    if (t == 255) g_bsum[b] = sh[255];
}
/* block 0: scan of g_bsum; block 1: scan of g_gcnt -> g_gstart */
__global__ void k_scan_b2() {
    __shared__ int sh[256];
    int t = threadIdx.x;
    int v;
    if (blockIdx.x == 0) v = (t < SCANB) ? g_bsum[t] : 0;
    else                 v = g_gcnt[t];
    sh[t] = v;
    __syncthreads();
    for (int o = 1; o < 256; o <<= 1) {
        int add = (t >= o) ? sh[t - o] : 0;
        __syncthreads();
        sh[t] += add;
        __syncthreads();
    }
    if (blockIdx.x == 0) { if (t < SCANB) g_bsum[t] = sh[t] - v; }
    else                 g_gstart[t] = sh[t] - v;
}
/* scan finalize + prep (merged) */
__global__ void k_scan_c() {
    int i = blockIdx.x * blockDim.x + threadIdx.x;
    if (i <= NN) {
        int off = g_off[i] + g_bsum[i >> 8];
        g_off[i] = off;
        if (i < NN) {
            g_cur[i] = off;
            int d = g_deg[i];
            g_invdeg[i] = 1.0f / (float)(d > 0 ? d : 1);
        }
    }
}

__global__ void k_scatter(const int* __restrict__ ei) {
    int e = blockIdx.x * blockDim.x + threadIdx.x;
    if (e >= EE) return;
    int d = ei[EE + e];
    int pos = atomicAdd(&g_cur[d], 1);
    g_srcs[pos] = ei[e];
}

__global__ void k_sortseg() {
    int n = blockIdx.x * blockDim.x + threadIdx.x;
    if (n >= NN) return;
    int beg = g_off[n], end = g_off[n + 1];
    for (int i = beg + 1; i < end; i++) {
        int v = g_srcs[i];
        int j = i - 1;
        while (j >= beg && g_srcs[j] > v) { g_srcs[j + 1] = g_srcs[j]; j--; }
        g_srcs[j + 1] = v;
    }
}

/* B pack over 32 K32-stages (W single fp16, activations carry the 2-term split):
   regions reg = s>>3: 0:hin_hi*Wr 1:hin_lo*Wr 2:agg_hi*Wl 3:agg_lo*Wl */
__global__ void k_bpack(const float* __restrict__ Wl, const float* __restrict__ Wr) {
    int idx = blockIdx.x * blockDim.x + threadIdx.x;
    if (idx >= LL * NSTAGE * 2 * 4096) return;
    int kk = idx & 31;
    int row = (idx >> 5) & 127;
    int bn = (idx >> 12) & 1;
    int rest = idx >> 13;
    int s = rest % NSTAGE;
    int l = rest / NSTAGE;
    int reg = s >> 3;
    int wk = (s & 7) * 32 + kk;
    int n = bn * 128 + row;
    const float* W = (reg < 2) ? Wr : Wl;
    float w = W[((size_t)l * 256 + wk) * 256 + n];
    size_t cb = ((size_t)((l * NSTAGE + s) * 2 + bn)) * 8192;
    *(__half*)((char*)g_Bpack + cb + slab_off(row, kk)) = __float2half_rn(w);
}

/* mean-aggregate neighbors -> hi/lo fp16 into g_aggT slab layout.
   One block per node, 64 threads x float4 (4 channels each). */
__global__ __launch_bounds__(64) void k_aggregate(const float* __restrict__ hprev) {
    int n = blockIdx.x;
    int t = threadIdx.x;        /* 0..63 */
    int c = t * 4;
    int beg = g_off[n], end = g_off[n + 1];
    float s0 = 0.0f, s1 = 0.0f, s2 = 0.0f, s3 = 0.0f;
    for (int i = beg; i < end; i++) {
        float4 v = *(const float4*)(hprev + (size_t)g_srcs[i] * F2C + c);
        s0 += v.x; s1 += v.y; s2 += v.z; s3 += v.w;
    }
    float inv = g_invdeg[n];
    float a0 = s0 * inv, a1 = s1 * inv, a2 = s2 * inv, a3 = s3 * inv;
    __half h0 = __float2half_rn(a0), h1 = __float2half_rn(a1);
    __half h2 = __float2half_rn(a2), h3 = __float2half_rn(a3);
    __half l0 = __float2half_rn(a0 - __half2float(h0));
    __half l1 = __float2half_rn(a1 - __half2float(h1));
    __half l2 = __float2half_rn(a2 - __half2float(h2));
    __half l3 = __float2half_rn(a3 - __half2float(h3));
    uint2 hp, lp;
    hp.x = (uint32_t)__half_as_ushort(h0) | ((uint32_t)__half_as_ushort(h1) << 16);
    hp.y = (uint32_t)__half_as_ushort(h2) | ((uint32_t)__half_as_ushort(h3) << 16);
    lp.x = (uint32_t)__half_as_ushort(l0) | ((uint32_t)__half_as_ushort(l1) << 16);
    lp.y = (uint32_t)__half_as_ushort(l2) | ((uint32_t)__half_as_ushort(l3) << 16);
    size_t cb = ((size_t)(n >> 7) * 16 + (c >> 5)) * 8192;
    uint32_t off = slab_off(n & 127, c & 31);
    *(uint2*)((char*)g_aggT + cb + off) = hp;
    *(uint2*)((char*)g_aggT + cb + 8 * 8192 + off) = lp;
}

/* ---------------- SAGE GEMM: warp-specialized producer + mbarrier ring ----------------
   C[128,128] = A''[128,1024] @ B''[1024,128], grid (391, 2).
   Warps 0..7 compute; warp 8 issues bulk copies. 6-slot ring, full/empty mbarriers. */
__global__ __launch_bounds__(288, 2)
void k_sage_mma(int layer, const float* __restrict__ bl,
                float* __restrict__ hnext,
                const __half* __restrict__ hin_in,
                __half* __restrict__ hin_out) {
    extern __shared__ char smem[];
    __shared__ float sbias[128];
    __shared__ __align__(8) unsigned long long mb_full[NSLOT], mb_empty[NSLOT];
    const int tid = threadIdx.x;
    const int wid = tid >> 5;
    const int lane = tid & 31;
    const int nb = blockIdx.x;
    const int bm = nb * MT;
    const int bn = blockIdx.y;
    const uint32_t sb = smem_u32(smem);

    if (tid == 0) {
#pragma unroll
        for (int i = 0; i < NSLOT; i++) {
            mbar_init(smem_u32(&mb_full[i]), 1);
            mbar_init(smem_u32(&mb_empty[i]), 8);
        }
    }
    if (tid < 128) sbias[tid] = bl[bn * 128 + tid];
    __syncthreads();

    float acc[2][8][4];
#pragma unroll
    for (int i = 0; i < 2; i++)
#pragma unroll
        for (int j = 0; j < 8; j++)
#pragma unroll
            for (int q = 0; q < 4; q++) acc[i][j][q] = 0.0f;

    if (wid == 8) {
        /* producer warp: one elected thread issues all copies */
        if (lane == 0) {
            int slot = 0, pe = 1;
            for (int s = 0; s < NSTAGE; s++) {
                if (s >= NSLOT) mbar_wait(smem_u32(&mb_empty[slot]), pe);
                uint32_t mb = smem_u32(&mb_full[slot]);
                mbar_expect(mb, 16384);
                int reg = s >> 3;
                int j = s & 7;
                int chunk = (reg & 1) ? 8 + j : j;
                const __half* base = (reg < 2) ? hin_in : g_aggT;
                bulkcp(sb + slot * 16384, base + ((size_t)(nb * 16 + chunk)) * 4096, 8192, mb);
                const __half* bsrc =
                    g_Bpack + ((size_t)((layer * NSTAGE + s) * 2 + bn)) * 4096;
                bulkcp(sb + slot * 16384 + 8192, bsrc, 8192, mb);
                if (++slot == NSLOT) { slot = 0; pe ^= 1; }
            }
        }
    } else {
        const int wm = wid >> 1;
        const int wn = wid & 1;
        const int rowlane = lane & 15;
        const int c16 = lane >> 4;

        int slot = 0, pf = 0;
        for (int s = 0; s < NSTAGE; s++) {
            mbar_wait(smem_u32(&mb_full[slot]), pf);
            uint32_t Abase = sb + slot * 16384;
            uint32_t Bbase = Abase + 8192;
#pragma unroll
            for (int ks = 0; ks < 2; ks++) {
                uint32_t a[2][4], bb[4][4];
#pragma unroll
                for (int mi = 0; mi < 2; mi++) {
                    int row = wm * 32 + mi * 16 + rowlane;
                    int c = ks * 2 + c16;
                    LDSM4(a[mi], Abase + row * 64 + ((c ^ ((row & 6) >> 1)) << 4));
                }
#pragma unroll
                for (int nj = 0; nj < 4; nj++) {
                    int row = wn * 64 + nj * 16 + rowlane;
                    int c = ks * 2 + c16;
                    LDSM4(bb[nj], Bbase + row * 64 + ((c ^ ((row & 6) >> 1)) << 4));
                }
#pragma unroll
                for (int mi = 0; mi < 2; mi++)
#pragma unroll
                    for (int nj = 0; nj < 4; nj++) {
                        MMA16816(acc[mi][nj * 2], a[mi], bb[nj][0], bb[nj][2]);
                        MMA16816(acc[mi][nj * 2 + 1], a[mi], bb[nj][1], bb[nj][3]);
                    }
            }
            if (lane == 0) mbar_arrive(smem_u32(&mb_empty[slot]));
            if (++slot == NSLOT) { slot = 0; pf ^= 1; }
        }
    }
    __syncthreads();

    /* acc -> smem Cs */
    float* Cs = (float*)smem;
    if (wid != 8) {
        const int wm = wid >> 1, wn = wid & 1;
#pragma unroll
        for (int mi = 0; mi < 2; mi++)
#pragma unroll
            for (int jn = 0; jn < 8; jn++) {
                int r1 = wm * 32 + mi * 16 + (lane >> 2);
                int cc = wn * 64 + jn * 8 + (lane & 3) * 2;
                Cs[r1 * 132 + cc]           = acc[mi][jn][0];
                Cs[r1 * 132 + cc + 1]       = acc[mi][jn][1];
                Cs[(r1 + 8) * 132 + cc]     = acc[mi][jn][2];
                Cs[(r1 + 8) * 132 + cc + 1] = acc[mi][jn][3];
            }
    }
    __syncthreads();

    /* epilogue: bias + leaky+residual, write hnext (+ hin slabs except last layer) */
    const bool wantHin = (layer != LL - 1);
    if (tid < 256) {
#pragma unroll 1
        for (int it = 0; it < 16; it++) {
            int idx = tid + it * 256;
            int row = idx >> 5;
            int c4 = (idx & 31) * 4;
            int gr = bm + row;
            if (gr < NN) {
                float x0 = Cs[row * 132 + c4 + 0] + sbias[c4 + 0];
                float x1 = Cs[row * 132 + c4 + 1] + sbias[c4 + 1];
                float x2 = Cs[row * 132 + c4 + 2] + sbias[c4 + 2];
                float x3 = Cs[row * 132 + c4 + 3] + sbias[c4 + 3];
                x0 = (x0 > 0.0f) ? 2.0f * x0 : (1.0f + NEGS) * x0;
                x1 = (x1 > 0.0f) ? 2.0f * x1 : (1.0f + NEGS) * x1;
                x2 = (x2 > 0.0f) ? 2.0f * x2 : (1.0f + NEGS) * x2;
                x3 = (x3 > 0.0f) ? 2.0f * x3 : (1.0f + NEGS) * x3;
                int col = bn * 128 + c4;
                *(float4*)(hnext + (size_t)gr * 256 + col) = make_float4(x0, x1, x2, x3);
                if (wantHin) {
                    __half h0 = __float2half_rn(x0), h1 = __float2half_rn(x1);
                    __half h2 = __float2half_rn(x2), h3 = __float2half_rn(x3);
                    uint2 hu, lu;
                    hu.x = (uint32_t)__half_as_ushort(h0) | ((uint32_t)__half_as_ushort(h1) << 16);
                    hu.y = (uint32_t)__half_as_ushort(h2) | ((uint32_t)__half_as_ushort(h3) << 16);
                    __half q0 = __float2half_rn(x0 - __half2float(h0));
                    __half q1 = __float2half_rn(x1 - __half2float(h1));
                    __half q2 = __float2half_rn(x2 - __half2float(h2));
                    __half q3 = __float2half_rn(x3 - __half2float(h3));
                    lu.x = (uint32_t)__half_as_ushort(q0) | ((uint32_t)__half_as_ushort(q1) << 16);
                    lu.y = (uint32_t)__half_as_ushort(q2) | ((uint32_t)__half_as_ushort(q3) << 16);
                    size_t cb = ((size_t)(gr >> 7) * 16 + (col >> 5)) * 8192;
                    uint32_t off = slab_off(gr & 127, col & 31);
                    *(uint2*)((char*)hin_out + cb + off) = hu;
                    *(uint2*)((char*)hin_out + cb + 8 * 8192 + off) = lu;
                }
            }
        }
    }
}

/* ---------------- fused head: GraphNorm + SoftmaxAggregation + 3-layer MLP ----------------
   One block per graph b, 256 threads. g/y1/y2 live in smem. */
__global__ __launch_bounds__(256) void k_head(
    const float* __restrict__ gw, const float* __restrict__ gb,
    const float* __restrict__ gs, const float* __restrict__ tptr,
    const float* __restrict__ W1, const float* __restrict__ b1,
    const float* __restrict__ W2, const float* __restrict__ b2,
    const float* __restrict__ W3, const float* __restrict__ b3,
    float* __restrict__ out) {
    __shared__ float sg[F2C];
    __shared__ float sy1[F2C];
    __shared__ float sy2[FF];
    int b = blockIdx.x;
    int c = threadIdx.x;
    int start = g_gstart[b], cnt = g_gcnt[b];
    float cntf = (cnt > 0) ? (float)cnt : 1.0f;
    float t = tptr[0];

    /* GraphNorm (per channel c) */
    float s = 0.0f;
    for (int i = 0; i < cnt; i++) s += g_hA[(size_t)(start + i) * F2C + c];
    float ms = (s / cntf) * gs[c];

    float v = 0.0f;
    for (int i = 0; i < cnt; i++) {
        float o = g_hA[(size_t)(start + i) * F2C + c] - ms;
        v += o * o;
    }
    float inv = 1.0f / sqrtf(v / cntf + EPSV);
    float w = gw[c], bias = gb[c];
    float m = -FLT_MAX;
    for (int i = 0; i < cnt; i++) {
        size_t idx = (size_t)(start + i) * F2C + c;
        float hv = w * (g_hA[idx] - ms) * inv + bias;
        g_hA[idx] = hv;
        m = fmaxf(m, hv * t);
    }

    /* softmax aggregation -> g */
    float se = 0.0f, sh = 0.0f;
    for (int i = 0; i < cnt; i++) {
        float hv = g_hA[(size_t)(start + i) * F2C + c];
        float e = expf(hv * t - m);
        se += e;
        sh += e * hv;
    }
    sg[c] = (cnt > 0) ? (sh / se) : 0.0f;
    __syncthreads();

    /* MLP1: y1 = leaky(g @ W1 + b1), 256 wide */
    {
        float acc = b1[c];
#pragma unroll 8
        for (int k = 0; k < F2C; k++) acc += sg[k] * W1[k * F2C + c];
        sy1[c] = (acc > 0.0f) ? acc : NEGS * acc;
    }
    __syncthreads();

    /* MLP2: y2 = leaky(y1 @ W2 + b2), 128 wide */
    if (c < FF) {
        float acc = b2[c];
#pragma unroll 8
        for (int k = 0; k < F2C; k++) acc += sy1[k] * W2[k * FF + c];
        sy2[c] = (acc > 0.0f) ? acc : NEGS * acc;
    }
    __syncthreads();

    /* MLP3: out = y2 @ W3 + b3, 2016 wide (8 cols per thread) */
    {
        float acc[8];
#pragma unroll
        for (int r = 0; r < 8; r++) {
            int idx = c + 256 * r;
            acc[r] = (idx < AA) ? b3[idx] : 0.0f;
        }
        for (int k = 0; k < FF; k++) {
            float rv = sy2[k];
            const float* wr = W3 + (size_t)k * AA;
#pragma unroll
            for (int r = 0; r < 8; r++) {
                int idx = c + 256 * r;
                if (idx < AA) acc[r] += rv * wr[idx];
            }
        }
#pragma unroll
        for (int r = 0; r < 8; r++) {
            int idx = c + 256 * r;
            if (idx < AA) out[b * AA + idx] = acc[r];
        }
    }
}

/* ---------------- launch ---------------- */
extern "C" void kernel_launch(void* const* d_in, const int* in_sizes, int n_in,
                              void* d_out, int out_size) {
    const int*   x     = (const int*)d_in[0];
    const int*   ei    = (const int*)d_in[1];
    const int*   batch = (const int*)d_in[2];
    const float* emb   = (const float*)d_in[3];
    const float* Wl    = (const float*)d_in[4];
    const float* bl    = (const float*)d_in[5];
    const float* Wr    = (const float*)d_in[6];
    const float* gw    = (const float*)d_in[7];
    const float* gb    = (const float*)d_in[8];
    const float* gs    = (const float*)d_in[9];
    const float* t     = (const float*)d_in[10];
    const float* W1    = (const float*)d_in[11];
    const float* b1    = (const float*)d_in[12];
    const float* W2    = (const float*)d_in[13];
    const float* b2    = (const float*)d_in[14];
    const float* W3    = (const float*)d_in[15];
    const float* b3    = (const float*)d_in[16];
    float* out = (float*)d_out;

    cudaFuncSetAttribute(k_sage_mma, cudaFuncAttributeMaxDynamicSharedMemorySize, SMEMB);

    __half* hinbuf[2];
    cudaGetSymbolAddress((void**)&hinbuf[0], g_hinA);
    cudaGetSymbolAddress((void**)&hinbuf[1], g_hinB);
    float* hbuf[2];
    cudaGetSymbolAddress((void**)&hbuf[0], g_hA);
    cudaGetSymbolAddress((void**)&hbuf[1], g_hB);

    /* graph structure + packing */
    k_zero<<<(NN + 255) / 256, 256>>>();
    k_embed<<<(NN * F2C + 255) / 256, 256>>>(x, emb);
    k_deg<<<(EE + 255) / 256, 256>>>(ei, batch);
    k_scan_a<<<SCANB, 256>>>();
    k_scan_b2<<<2, 256>>>();
    k_scan_c<<<(NN + 1 + 255) / 256, 256>>>();
    k_scatter<<<(EE + 255) / 256, 256>>>(ei);
    k_sortseg<<<(NN + 255) / 256, 256>>>();
    k_bpack<<<(LL * NSTAGE * 2 * 4096 + 255) / 256, 256>>>(Wl, Wr);

    /* 10 SAGE layers: aggregate + warp-specialized tensor GEMM (fp16 2-term, K''=1024) */
    dim3 ggrid(NB, 2);
    for (int l = 0; l < LL; l++) {
        int p = l & 1;
        k_aggregate<<<NN, 64>>>((const float*)hbuf[p]);
        k_sage_mma<<<ggrid, 288, SMEMB>>>(l, bl + l * F2C, hbuf[p ^ 1],
                                          hinbuf[p], hinbuf[p ^ 1]);
    }

    /* fused GraphNorm + softmax aggregation + MLP head */
    k_head<<<BB, 256>>>(gw, gb, gs, t, W1, b1, W2, b2, W3, b3, out);
}